// round 16
// baseline (speedup 1.0000x reference)
#include <cuda_runtime.h>

// Problem constants
#define Bc 64
#define Kc 5
#define Hc 320
#define Wc 320
#define Nc (Hc * Wc)        // 102400 pixels per (b,k)
#define NGc (Nc / 4)        // 25600 float4 groups
#define BPB 50              // blocks per batch; each 128-thread block owns 512 groups
#define THREADS 128
#define TOTAL_BLOCKS (Bc * BPB)
#define NACC 23             // 5*(S,I,XS,XF) + spsum + tabs + tfg
#define ROW 24              // scratch row stride (floats)

// Per-block partial sums: [b*BPB+block][ROW]. Overwritten every launch.
__device__ float g_scratch[TOTAL_BLOCKS * ROW];
// Per-batch losses.
__device__ float g_loss[Bc];
// Per-batch done-counters (wrap at BPB) and ready-flags. Flags follow a strict
// producer/consumer alternation: main's last block of batch b sets flag_b=1
// (after a release fence); final block b consumes it and resets it to 0, so
// every graph replay starts from the same all-zero state.
__device__ unsigned int g_cnt_b[Bc];
__device__ unsigned int g_flag_b[Bc];
// Global counter for the cross-batch sum (wraps at Bc).
__device__ unsigned int g_cnt;

// Per-element update. 2 MUFU ops (EX2, RCP); softplus sum deferred via
// sum log(u) = log(prod u), u in (1,2] (one LG2 per 20-mul chain; product of
// 40 u's <= 2^40, rel err ~2.4e-6). MUFU.RCP mandatory for argmin precision.
// BCE identity: sum max(x,0) = 0.5*(sum x + sum |x|).
__device__ __forceinline__ void elem(float x, float fg,
                                     float& S, float& I, float& XS, float& XF,
                                     float& prod, float& tabs)
{
    const float t  = fabsf(x);
    const float e  = __expf(-t);                 // FMUL + MUFU.EX2
    const float u  = 1.0f + e;
    const float rc = __fdividef(1.0f, u);        // MUFU.RCP
    const float p  = (x >= 0.0f) ? rc : (1.0f - rc);   // sigmoid(x)

    prod *= u;                                   // deferred log
    tabs += t;
    S    += p;
    I     = fmaf(p, fg, I);
    XS   += x;
    XF    = fmaf(x, fg, XF);
}

#define ELEM4(xv, fgv, k, pr) \
    elem((xv).x, (fgv).x, acc[(k)*4+0], acc[(k)*4+1], acc[(k)*4+2], acc[(k)*4+3], pr, acc[21]); \
    elem((xv).y, (fgv).y, acc[(k)*4+0], acc[(k)*4+1], acc[(k)*4+2], acc[(k)*4+3], pr, acc[21]); \
    elem((xv).z, (fgv).z, acc[(k)*4+0], acc[(k)*4+1], acc[(k)*4+2], acc[(k)*4+3], pr, acc[21]); \
    elem((xv).w, (fgv).w, acc[(k)*4+0], acc[(k)*4+1], acc[(k)*4+2], acc[(k)*4+3], pr, acc[21]);

// Hot-loop kernel: byte-identical per-thread code to the proven 37.4us kernel;
// the only addition is a tiny per-batch counter/flag tail (fence + atomic).
__global__ __launch_bounds__(THREADS)
void hung_main(const float* __restrict__ slot, const float* __restrict__ tgt)
{
    const int b = blockIdx.y;
    const int tid = threadIdx.x;

    float acc[NACC];
#pragma unroll
    for (int i = 0; i < NACC; i++) acc[i] = 0.0f;

    const float4* tg4 = reinterpret_cast<const float4*>(tgt) + (size_t)b * NGc;
    const float4* sl4 = reinterpret_cast<const float4*>(slot) + (size_t)b * Kc * NGc;

    const int base = blockIdx.x * (NGc / BPB);   // 512 groups per block

    // Two iterations; each explicitly batches 12 independent LDG.128s before
    // any compute (MLP=12). unroll 1 stops ptxas from merging iterations into
    // a 24-deep front batch (L1tex-queue contention pathology).
#pragma unroll 1
    for (int it = 0; it < 2; it++) {
        const int g0 = base + it * (2 * THREADS) + tid;
        const int g1 = g0 + THREADS;

        const float4 fgA = __ldg(&tg4[g0]);
        const float4 fgB = __ldg(&tg4[g1]);
        float4 xa[Kc], xb[Kc];
#pragma unroll
        for (int k = 0; k < Kc; k++) {
            xa[k] = __ldg(&sl4[(size_t)k * NGc + g0]);
            xb[k] = __ldg(&sl4[(size_t)k * NGc + g1]);
        }

        acc[22] += ((fgA.x + fgA.y) + (fgA.z + fgA.w))
                 + ((fgB.x + fgB.y) + (fgB.z + fgB.w));   // tfg

        float prodA = 1.0f, prodB = 1.0f;        // two parallel 20-mul chains
#pragma unroll
        for (int k = 0; k < Kc; k++) {
            ELEM4(xa[k], fgA, k, prodA)
            ELEM4(xb[k], fgB, k, prodB)
        }
        acc[20] += __logf(prodA * prodB);        // one LG2 per 40 elements
    }

    // Block reduction: warp shuffle then cross-warp via shared (deterministic).
#pragma unroll
    for (int i = 0; i < NACC; i++) {
        float v = acc[i];
#pragma unroll
        for (int o = 16; o > 0; o >>= 1) v += __shfl_xor_sync(0xffffffffu, v, o);
        acc[i] = v;
    }
    __shared__ float sm[THREADS / 32][NACC];
    const int warp = tid >> 5, lane = tid & 31;
    if (lane == 0) {
#pragma unroll
        for (int i = 0; i < NACC; i++) sm[warp][i] = acc[i];
    }
    __syncthreads();
    if (tid < NACC) {
        float s = 0.0f;
#pragma unroll
        for (int w = 0; w < THREADS / 32; w++) s += sm[w][tid];
        g_scratch[((size_t)b * BPB + blockIdx.x) * ROW + tid] = s;
    }

    // Per-batch completion: last block of batch b raises the ready flag
    // (threadFenceReduction pattern: block stores -> syncthreads -> release
    // fence -> atomic).
    __syncthreads();
    if (tid == 0) {
        __threadfence();
        if (atomicInc(&g_cnt_b[b], BPB - 1) == BPB - 1)
            atomicExch(&g_flag_b[b], 1u);
    }
}

// Concurrent finalize: launched as a PARALLEL graph branch (forked stream).
// Block b spin-waits on batch b's flag, so per-batch losses are computed
// WHILE main is still streaming later batches; only the last batch's loss and
// the 64-way sum remain exposed after main drains (~1.5us vs the old ~6.5us
// serialized node). Spin is bounded so a serialized-profiling replay cannot
// hang the container (timing/correctness runs always see the flag).
__global__ __launch_bounds__(64)
void hung_final(float* __restrict__ out)
{
    const int b = blockIdx.x;
    const int tid = threadIdx.x;

    __shared__ float sa[NACC];
    __shared__ unsigned int s_last;

    if (tid == 0) {
        for (long i = 0; i < 2000000; i++) {       // bounded ~0.4s failsafe
            if (atomicOr(&g_flag_b[b], 0u) != 0u) break;
            __nanosleep(200);
        }
        atomicExch(&g_flag_b[b], 0u);              // reset for next replay
        __threadfence();                           // acquire side
    }
    __syncthreads();

    if (tid < NACC) {
        float v = 0.0f;
#pragma unroll
        for (int j = 0; j < BPB; j++)
            v += __ldcg(&g_scratch[((size_t)b * BPB + j) * ROW + tid]);
        sa[tid] = v;
    }
    __syncthreads();

    if (tid == 0) {
        const float* a = sa;
        const float Tfg   = a[22];
        const float Tbg   = (float)Nc - Tfg;
        const float spsum = a[20];
        const float tabs  = a[21];
        float sumXS = 0.0f, sumXF = 0.0f;
        float best = 3.4e38f, selXS = 0.0f, selXF = 0.0f;
#pragma unroll
        for (int k = 0; k < Kc; k++) {
            const float S  = a[k*4+0];
            const float I  = a[k*4+1];
            const float XS = a[k*4+2];
            const float XF = a[k*4+3];
            const float Ib = S - I;
            const float cfg = 1.0f - I  / (S + Tfg - I  + 1e-6f);
            const float cbg = 1.0f - Ib / (S + Tbg - Ib + 1e-6f);
            const float score = cfg - cbg;   // perm cost differs only by this term
            if (score < best) { best = score; selXS = XS; selXF = XF; }  // ties -> smallest k
            sumXS += XS; sumXF += XF;
        }
        const float Ctot = spsum + 0.5f * (sumXS + tabs);  // sum max(x,0) + sum softplus
        // loss_b = Ctot - [XF_k0 + sum_{k!=k0}(XS_k - XF_k)]
        g_loss[b] = Ctot - sumXS + sumXF + selXS - 2.0f * selXF;
        __threadfence();
        s_last = (atomicInc(&g_cnt, Bc - 1) == Bc - 1) ? 1u : 0u;
    }
    __syncthreads();
    if (s_last == 0u) return;

    // Globally last finisher: sum the 64 per-batch losses (L2-resident).
    float l = (tid < Bc) ? __ldcg(&g_loss[tid]) : 0.0f;
#pragma unroll
    for (int o = 16; o > 0; o >>= 1) l += __shfl_xor_sync(0xffffffffu, l, o);
    __shared__ float wsum[2];
    if ((tid & 31) == 0) wsum[tid >> 5] = l;
    __syncthreads();
    if (tid == 0)
        out[0] = (wsum[0] + wsum[1]) * (1.0f / ((float)Bc * (float)Kc * (float)Nc));
}

extern "C" void kernel_launch(void* const* d_in, const int* in_sizes, int n_in,
                              void* d_out, int out_size)
{
    // metadata order: fg_logits (unused by reference), slot_logits, target
    const float* slot = (const float*)d_in[1];
    const float* tgt  = (const float*)d_in[2];
    float* out = (float*)d_out;

    // Fork a parallel branch for the concurrent finalize. Streams/events are
    // host-side objects (no device memory); kernel_launch is invoked only a
    // handful of times, so leaking them is harmless, and destroying a stream
    // mid-capture would invalidate the capture.
    cudaStream_t s2;
    cudaEvent_t eFork, eJoin;
    cudaStreamCreateWithFlags(&s2, cudaStreamNonBlocking);
    cudaEventCreateWithFlags(&eFork, cudaEventDisableTiming);
    cudaEventCreateWithFlags(&eJoin, cudaEventDisableTiming);

    cudaEventRecord(eFork, 0);                 // fork point on capture stream
    cudaStreamWaitEvent(s2, eFork, 0);

    hung_final<<<Bc, 64, 0, s2>>>(out);        // parallel branch: spins per batch

    dim3 grid(BPB, Bc);
    hung_main<<<grid, THREADS>>>(slot, tgt);   // main branch

    cudaEventRecord(eJoin, s2);                // join branches
    cudaStreamWaitEvent(0, eJoin, 0);
}

// round 17
// speedup vs baseline: 1.1045x; 1.1045x over previous
#include <cuda_runtime.h>

// Problem constants
#define Bc 64
#define Kc 5
#define Hc 320
#define Wc 320
#define Nc (Hc * Wc)        // 102400 pixels per (b,k)
#define NGc (Nc / 4)        // 25600 float4 groups
#define BPB 50              // blocks per batch; each 128-thread block owns 512 groups
#define THREADS 128
#define TOTAL_BLOCKS (Bc * BPB)
#define NACC 23             // 5*(S,I,XS,XF) + spsum + tabs + tfg
#define ROW 24              // scratch row stride (floats)

// Per-block partial sums: [b*BPB+block][ROW]. Overwritten every launch.
__device__ float g_scratch[TOTAL_BLOCKS * ROW];
// Per-batch losses + last-block counter for the finalize kernel.
__device__ float g_loss[Bc];
// atomicInc with limit Bc-1 wraps to 0 after exactly Bc increments ->
// self-resetting across graph replays.
__device__ unsigned int g_cnt = 0;

// Per-element update. 2 MUFU ops (EX2, RCP); softplus sum deferred via
// sum log(u) = log(prod u), u in (1,2] (one LG2 per 20-mul chain; product of
// 40 u's <= 2^40, rel err ~2.4e-6). MUFU.RCP mandatory for argmin precision
// (approx reciprocal flipped a near-tied argmin in R10 -> rel_err 4.4e-4).
// BCE identity: sum max(x,0) = 0.5*(sum x + sum |x|).
__device__ __forceinline__ void elem(float x, float fg,
                                     float& S, float& I, float& XS, float& XF,
                                     float& prod, float& tabs)
{
    const float t  = fabsf(x);
    const float e  = __expf(-t);                 // FMUL + MUFU.EX2
    const float u  = 1.0f + e;
    const float rc = __fdividef(1.0f, u);        // MUFU.RCP
    const float p  = (x >= 0.0f) ? rc : (1.0f - rc);   // sigmoid(x)

    prod *= u;                                   // deferred log
    tabs += t;
    S    += p;
    I     = fmaf(p, fg, I);
    XS   += x;
    XF    = fmaf(x, fg, XF);
}

#define ELEM4(xv, fgv, k, pr) \
    elem((xv).x, (fgv).x, acc[(k)*4+0], acc[(k)*4+1], acc[(k)*4+2], acc[(k)*4+3], pr, acc[21]); \
    elem((xv).y, (fgv).y, acc[(k)*4+0], acc[(k)*4+1], acc[(k)*4+2], acc[(k)*4+3], pr, acc[21]); \
    elem((xv).z, (fgv).z, acc[(k)*4+0], acc[(k)*4+1], acc[(k)*4+2], acc[(k)*4+3], pr, acc[21]); \
    elem((xv).w, (fgv).w, acc[(k)*4+0], acc[(k)*4+1], acc[(k)*4+2], acc[(k)*4+3], pr, acc[21]);

// Hot-loop kernel — the proven 37.4us artifact (validated identically in
// R8/R13/R15). Two iterations, each an explicit batch of 12 independent
// LDG.128s (MLP=12) before any compute; 128-thread CTAs; standalone kernel
// (fusing ANY tail perturbs ptxas whole-kernel regalloc: 48 regs serializes
// the batch, 128 regs collapses occupancy); no launch_bounds min-blocks.
// DRAM-bound at ~5.2TB/s (~85% of practical HBM roofline); MUFU reduction
// and occupancy changes measured neutral.
__global__ __launch_bounds__(THREADS)
void hung_main(const float* __restrict__ slot, const float* __restrict__ tgt)
{
    const int b = blockIdx.y;
    const int tid = threadIdx.x;

    float acc[NACC];
#pragma unroll
    for (int i = 0; i < NACC; i++) acc[i] = 0.0f;

    const float4* tg4 = reinterpret_cast<const float4*>(tgt) + (size_t)b * NGc;
    const float4* sl4 = reinterpret_cast<const float4*>(slot) + (size_t)b * Kc * NGc;

    const int base = blockIdx.x * (NGc / BPB);   // 512 groups per block

    // unroll 1 stops ptxas from merging iterations into a 24-deep front batch
    // (cross-CTA L1tex-queue contention pathology, R4 = 54us).
#pragma unroll 1
    for (int it = 0; it < 2; it++) {
        const int g0 = base + it * (2 * THREADS) + tid;
        const int g1 = g0 + THREADS;

        const float4 fgA = __ldg(&tg4[g0]);
        const float4 fgB = __ldg(&tg4[g1]);
        float4 xa[Kc], xb[Kc];
#pragma unroll
        for (int k = 0; k < Kc; k++) {
            xa[k] = __ldg(&sl4[(size_t)k * NGc + g0]);
            xb[k] = __ldg(&sl4[(size_t)k * NGc + g1]);
        }

        acc[22] += ((fgA.x + fgA.y) + (fgA.z + fgA.w))
                 + ((fgB.x + fgB.y) + (fgB.z + fgB.w));   // tfg

        float prodA = 1.0f, prodB = 1.0f;        // two parallel 20-mul chains
#pragma unroll
        for (int k = 0; k < Kc; k++) {
            ELEM4(xa[k], fgA, k, prodA)
            ELEM4(xb[k], fgB, k, prodB)
        }
        acc[20] += __logf(prodA * prodB);        // one LG2 per 40 elements
    }

    // Block reduction: warp shuffle then cross-warp via shared (deterministic).
#pragma unroll
    for (int i = 0; i < NACC; i++) {
        float v = acc[i];
#pragma unroll
        for (int o = 16; o > 0; o >>= 1) v += __shfl_xor_sync(0xffffffffu, v, o);
        acc[i] = v;
    }
    __shared__ float sm[THREADS / 32][NACC];
    const int warp = tid >> 5, lane = tid & 31;
    if (lane == 0) {
#pragma unroll
        for (int i = 0; i < NACC; i++) sm[warp][i] = acc[i];
    }
    __syncthreads();
    if (tid < NACC) {
        float s = 0.0f;
#pragma unroll
        for (int w = 0; w < THREADS / 32; w++) s += sm[w][tid];
        g_scratch[((size_t)b * BPB + blockIdx.x) * ROW + tid] = s;
    }
}

// Parallel finalize: 64 blocks (one per batch) x 64 threads.
// Each block reduces its 50x23 partials (~4.6KB, L2-hot) and computes the
// per-batch loss; the LAST block (atomic counter) sums the 64 losses.
// The ~6.5us cost is dominated by fixed kernel-node overhead (1-block,
// 64-block, PDL, and fork-overlap variants all measured 6.3-7.7us exposed).
__global__ __launch_bounds__(64)
void hung_final(float* __restrict__ out)
{
    const int b = blockIdx.x;
    const int tid = threadIdx.x;

    __shared__ float sa[NACC];
    __shared__ unsigned int s_last;

    if (tid < NACC) {
        float v = 0.0f;
#pragma unroll
        for (int j = 0; j < BPB; j++)
            v += g_scratch[((size_t)b * BPB + j) * ROW + tid];
        sa[tid] = v;
    }
    __syncthreads();

    if (tid == 0) {
        const float* a = sa;
        const float Tfg   = a[22];
        const float Tbg   = (float)Nc - Tfg;
        const float spsum = a[20];
        const float tabs  = a[21];
        float sumXS = 0.0f, sumXF = 0.0f;
        float best = 3.4e38f, selXS = 0.0f, selXF = 0.0f;
#pragma unroll
        for (int k = 0; k < Kc; k++) {
            const float S  = a[k*4+0];
            const float I  = a[k*4+1];
            const float XS = a[k*4+2];
            const float XF = a[k*4+3];
            const float Ib = S - I;
            const float cfg = 1.0f - I  / (S + Tfg - I  + 1e-6f);
            const float cbg = 1.0f - Ib / (S + Tbg - Ib + 1e-6f);
            const float score = cfg - cbg;   // perm cost differs only by this term
            if (score < best) { best = score; selXS = XS; selXF = XF; }  // ties -> smallest k
            sumXS += XS; sumXF += XF;
        }
        const float Ctot = spsum + 0.5f * (sumXS + tabs);  // sum max(x,0) + sum softplus
        // loss_b = Ctot - [XF_k0 + sum_{k!=k0}(XS_k - XF_k)]
        g_loss[b] = Ctot - sumXS + sumXF + selXS - 2.0f * selXF;
        __threadfence();
        s_last = (atomicInc(&g_cnt, Bc - 1) == Bc - 1) ? 1u : 0u;
    }
    __syncthreads();
    if (s_last == 0u) return;

    // Last block: sum the 64 per-batch losses (L2-resident).
    float l = (tid < Bc) ? __ldcg(&g_loss[tid]) : 0.0f;
#pragma unroll
    for (int o = 16; o > 0; o >>= 1) l += __shfl_xor_sync(0xffffffffu, l, o);
    __shared__ float wsum[2];
    if ((tid & 31) == 0) wsum[tid >> 5] = l;
    __syncthreads();
    if (tid == 0)
        out[0] = (wsum[0] + wsum[1]) * (1.0f / ((float)Bc * (float)Kc * (float)Nc));
}

extern "C" void kernel_launch(void* const* d_in, const int* in_sizes, int n_in,
                              void* d_out, int out_size)
{
    // metadata order: fg_logits (unused by reference), slot_logits, target
    const float* slot = (const float*)d_in[1];
    const float* tgt  = (const float*)d_in[2];
    float* out = (float*)d_out;

    dim3 grid(BPB, Bc);
    hung_main<<<grid, THREADS>>>(slot, tgt);
    hung_final<<<Bc, 64>>>(out);
}